// round 12
// baseline (speedup 1.0000x reference)
#include <cuda_runtime.h>
#include <cuda_bf16.h>
#include <math.h>
#include <stdint.h>

#define B_   64
#define L_   512
#define DQ_  2048
#define H_   128
#define KH_  128
#define DC_  512
#define DCQ_ 1536
#define R_   64

// ---------------- scratch (device globals; no allocation allowed) ----------
__device__ float g_qhk[B_ * H_ * KH_];
__device__ float g_Ah[H_ * KH_ * R_];
__device__ float g_qr[B_ * H_ * R_];
__device__ float g_kv[B_ * L_ * DC_];
__device__ float g_kvp[8 * B_ * DC_];
__device__ float g_kvsum[B_ * DC_];
__device__ float g_scores[B_ * H_ * DC_];
__device__ float g_ctx[B_ * H_ * DC_];
__device__ float g_ctxlat[B_ * H_ * KH_];
__device__ float g_part[4 * 1048576];
__device__ float g_rsin[L_ * DC_];
__device__ float g_rcos[L_ * DC_];

// ---------------- bf16 helpers ---------------------------------------------
__device__ __forceinline__ void bsplit4(float4 v, uint2& hi, uint2& lo) {
    uint32_t h01, h23, l01, l23;
    asm("cvt.rn.bf16x2.f32 %0, %1, %2;" : "=r"(h01) : "f"(v.y), "f"(v.x));
    asm("cvt.rn.bf16x2.f32 %0, %1, %2;" : "=r"(h23) : "f"(v.w), "f"(v.z));
    float r0 = v.x - __uint_as_float(h01 << 16);
    float r1 = v.y - __uint_as_float(h01 & 0xFFFF0000u);
    float r2 = v.z - __uint_as_float(h23 << 16);
    float r3 = v.w - __uint_as_float(h23 & 0xFFFF0000u);
    asm("cvt.rn.bf16x2.f32 %0, %1, %2;" : "=r"(l01) : "f"(r1), "f"(r0));
    asm("cvt.rn.bf16x2.f32 %0, %1, %2;" : "=r"(l23) : "f"(r3), "f"(r2));
    hi.x = h01; hi.y = h23; lo.x = l01; lo.y = l23;
}
__device__ __forceinline__ void bhi4(float4 v, uint2& hi) {
    uint32_t h01, h23;
    asm("cvt.rn.bf16x2.f32 %0, %1, %2;" : "=r"(h01) : "f"(v.y), "f"(v.x));
    asm("cvt.rn.bf16x2.f32 %0, %1, %2;" : "=r"(h23) : "f"(v.w), "f"(v.z));
    hi.x = h01; hi.y = h23;
}

#define LDMX4(r, a)                                                           \
    asm volatile("ldmatrix.sync.aligned.m8n8.x4.shared.b16 {%0,%1,%2,%3}, [%4];" \
                 : "=r"((r)[0]), "=r"((r)[1]), "=r"((r)[2]), "=r"((r)[3])     \
                 : "r"(a))
#define LDMX2(r, a)                                                           \
    asm volatile("ldmatrix.sync.aligned.m8n8.x2.shared.b16 {%0,%1}, [%2];"    \
                 : "=r"((r)[0]), "=r"((r)[1]) : "r"(a))
#define LDMX2T(r, a)                                                          \
    asm volatile("ldmatrix.sync.aligned.m8n8.x2.trans.shared.b16 {%0,%1}, [%2];" \
                 : "=r"((r)[0]), "=r"((r)[1]) : "r"(a))

#define MMAB(d, a, b)                                                         \
    asm volatile(                                                             \
        "mma.sync.aligned.m16n8k16.row.col.f32.bf16.bf16.f32 "                \
        "{%0,%1,%2,%3}, {%4,%5,%6,%7}, {%8,%9}, {%0,%1,%2,%3};"               \
        : "+f"((d)[0]), "+f"((d)[1]), "+f"((d)[2]), "+f"((d)[3])              \
        : "r"((a)[0]), "r"((a)[1]), "r"((a)[2]), "r"((a)[3]),                 \
          "r"((b)[0]), "r"((b)[1]))

// ---------------- split-bf16 mma.sync GEMM  (BM=32*MI, BN=32*NJ, BK=32) ----
// C[m,n] = sum_k A[m,k] * B[n,k].  TRANSB: B source [K,N] row-major.
// ALO=true : 3 MMAs/k16 (ah*bh + ah*bl + al*bh)  — full precision path.
// ALO=false: 2 MMAs/k16 (ah*bh + ah*bl), no A-lo plane — q-path only.
// 2-stage SMEM double buffer, prefetch distance 2. Split-K via blockIdx.z.
template <int MI, int NJ, bool TRANSB, bool BIAS, bool ALO>
__global__ __launch_bounds__(256)
void mgemm(const float* __restrict__ A, const float* __restrict__ Bm,
           float* __restrict__ C, const float* __restrict__ bias,
           float bscale, long sBiasz, int Kd,
           long sAz, long sBz, long sCz, int lda, int ldb, int ldc,
           int nspl, long sAsp, long sBsp, long sCsp) {
    constexpr int BM = 32 * MI, BN = 32 * NJ;
    constexpr int PA = 80;
    constexpr int PBT = BN * 2 + 16;
    constexpr int ASZ = BM * PA;
    constexpr int BSZ = TRANSB ? 32 * PBT : BN * PA;
    constexpr int APL = ALO ? 2 : 1;
    constexpr int A_HI = 0, A_LO = ASZ;
    constexpr int B_HI = APL * ASZ, B_LO = APL * ASZ + BSZ;
    constexpr int STAGE = APL * ASZ + 2 * BSZ;
    constexpr int N4 = BN / 4;
    constexpr int KSTEP_T = 256 / N4;

    extern __shared__ __align__(16) char sm[];

    const int tid = threadIdx.x, lane = tid & 31, wid = tid >> 5;
    const int wm = wid >> 2, wn = wid & 3;
    const int n0 = blockIdx.x * BN, m0 = blockIdx.y * BM;
    int bz = blockIdx.z, sp = 0;
    if (nspl > 1) { sp = bz % nspl; bz /= nspl; }

    const float* Ab = A + (long)bz * sAz + (long)sp * sAsp + (long)m0 * lda;
    const float* Bb = (TRANSB ? (Bm + (long)bz * sBz + (long)sp * sBsp + n0)
                              : (Bm + (long)bz * sBz + (long)sp * sBsp +
                                 (long)n0 * ldb));
    float* Cb = C + (long)bz * sCz + (long)sp * sCsp;

    float acc[MI][NJ][4];
#pragma unroll
    for (int mi = 0; mi < MI; mi++)
#pragma unroll
        for (int nj = 0; nj < NJ; nj++)
#pragma unroll
            for (int e = 0; e < 4; e++) acc[mi][nj][e] = 0.f;

    const int a_row0 = tid >> 3, a_c4 = tid & 7;
    const int bt_n4 = tid & (N4 - 1), bt_k0 = tid / N4;

    const int lane7 = lane & 7, laneb = (lane >> 3) & 1, lanet = lane >> 4;
    uint32_t aoff[MI][2], boff[NJ][2];
#pragma unroll
    for (int mi = 0; mi < MI; mi++)
#pragma unroll
        for (int s = 0; s < 2; s++)
            aoff[mi][s] = (uint32_t)((wm * (16 * MI) + mi * 16 + lane7 + laneb * 8) * PA +
                                     (s * 16 + lanet * 8) * 2);
#pragma unroll
    for (int nj = 0; nj < NJ; nj++)
#pragma unroll
        for (int s = 0; s < 2; s++) {
            if (TRANSB)
                boff[nj][s] = (uint32_t)((s * 16 + laneb * 8 + lane7) * PBT +
                                         (wn * (8 * NJ) + nj * 8) * 2);
            else
                boff[nj][s] = (uint32_t)((wn * (8 * NJ) + nj * 8 + lane7) * PA +
                                         (s * 16 + laneb * 8) * 2);
        }
    const uint32_t smb = (uint32_t)__cvta_generic_to_shared(sm);

    float4 pa[MI], pb[NJ];
    const int nch = Kd >> 5;

#define LDG_CH(k0v)                                                           \
    do {                                                                      \
        _Pragma("unroll")                                                     \
        for (int i = 0; i < MI; i++)                                          \
            pa[i] = *(const float4*)(Ab + (long)(a_row0 + i * 32) * lda +     \
                                     (k0v) + (a_c4 << 2));                    \
        if (!TRANSB) {                                                        \
            _Pragma("unroll")                                                 \
            for (int i = 0; i < NJ; i++)                                      \
                pb[i] = *(const float4*)(Bb + (long)(a_row0 + i * 32) * ldb + \
                                         (k0v) + (a_c4 << 2));                \
        } else {                                                              \
            _Pragma("unroll")                                                 \
            for (int i = 0; i < NJ; i++)                                      \
                pb[i] = *(const float4*)(Bb +                                 \
                         (long)((k0v) + bt_k0 + i * KSTEP_T) * ldb +          \
                         (bt_n4 << 2));                                       \
        }                                                                     \
    } while (0)

#define STS_CH(buf)                                                           \
    do {                                                                      \
        char* st = sm + (buf) * STAGE;                                        \
        _Pragma("unroll")                                                     \
        for (int i = 0; i < MI; i++) {                                        \
            int off = (a_row0 + i * 32) * PA + a_c4 * 8;                      \
            if (ALO) {                                                        \
                uint2 hi, lo;                                                 \
                bsplit4(pa[i], hi, lo);                                       \
                *(uint2*)(st + A_HI + off) = hi;                              \
                *(uint2*)(st + A_LO + off) = lo;                              \
            } else {                                                          \
                uint2 hi;                                                     \
                bhi4(pa[i], hi);                                              \
                *(uint2*)(st + A_HI + off) = hi;                              \
            }                                                                 \
        }                                                                     \
        _Pragma("unroll")                                                     \
        for (int i = 0; i < NJ; i++) {                                        \
            uint2 hi, lo;                                                     \
            bsplit4(pb[i], hi, lo);                                           \
            int off = TRANSB ? ((bt_k0 + i * KSTEP_T) * PBT + bt_n4 * 8)      \
                             : ((a_row0 + i * 32) * PA + a_c4 * 8);           \
            *(uint2*)(st + B_HI + off) = hi;                                  \
            *(uint2*)(st + B_LO + off) = lo;                                  \
        }                                                                     \
    } while (0)

    LDG_CH(0);
    STS_CH(0);
    if (nch > 1) LDG_CH(32);
    __syncthreads();

    for (int ch = 0; ch < nch; ch++) {
        const int cur = ch & 1;
        if (ch + 1 < nch) {
            STS_CH(1 - cur);
            if (ch + 2 < nch) LDG_CH((ch + 2) << 5);
        }
        const uint32_t sb = smb + cur * STAGE;
#pragma unroll
        for (int s = 0; s < 2; s++) {
            uint32_t ah[MI][4], al[ALO ? MI : 1][4], bh[NJ][2], bl[NJ][2];
#pragma unroll
            for (int mi = 0; mi < MI; mi++) {
                LDMX4(ah[mi], sb + A_HI + aoff[mi][s]);
                if (ALO) LDMX4(al[mi], sb + A_LO + aoff[mi][s]);
            }
#pragma unroll
            for (int nj = 0; nj < NJ; nj++) {
                if (TRANSB) {
                    LDMX2T(bh[nj], sb + B_HI + boff[nj][s]);
                    LDMX2T(bl[nj], sb + B_LO + boff[nj][s]);
                } else {
                    LDMX2(bh[nj], sb + B_HI + boff[nj][s]);
                    LDMX2(bl[nj], sb + B_LO + boff[nj][s]);
                }
            }
#pragma unroll
            for (int mi = 0; mi < MI; mi++)
#pragma unroll
                for (int nj = 0; nj < NJ; nj++) {
                    MMAB(acc[mi][nj], ah[mi], bh[nj]);
                    MMAB(acc[mi][nj], ah[mi], bl[nj]);
                    if (ALO) MMAB(acc[mi][nj], al[mi], bh[nj]);
                }
        }
        __syncthreads();
    }
#undef LDG_CH
#undef STS_CH

    const float* bias_b = BIAS ? (bias + (long)bz * sBiasz) : (const float*)0;
#pragma unroll
    for (int mi = 0; mi < MI; mi++)
#pragma unroll
        for (int nj = 0; nj < NJ; nj++) {
            int r = m0 + wm * (16 * MI) + mi * 16 + (lane >> 2);
            int c = n0 + wn * (8 * NJ) + nj * 8 + ((lane & 3) << 1);
            float2 v0 = make_float2(acc[mi][nj][0], acc[mi][nj][1]);
            float2 v1 = make_float2(acc[mi][nj][2], acc[mi][nj][3]);
            if (BIAS) {
                float b0 = bias_b[c] * bscale, b1 = bias_b[c + 1] * bscale;
                v0.x += b0; v0.y += b1; v1.x += b0; v1.y += b1;
            }
            *(float2*)&Cb[(long)r * ldc + c] = v0;
            *(float2*)&Cb[(long)(r + 8) * ldc + c] = v1;
        }
}

static inline int stage_bytes(int MI, int NJ, bool TB, bool ALO) {
    int asz = 32 * MI * 80;
    int bsz = TB ? 32 * (32 * NJ * 2 + 16) : 32 * NJ * 80;
    return (ALO ? 2 : 1) * asz + 2 * bsz;
}

// ---------------- RoPE table: sin/cos per (l, d) once ---------------------
__global__ __launch_bounds__(512) void rope_tab_kernel() {
    const int l = blockIdx.x;
    const int d = threadIdx.x;
    float ex = (float)(d & ~1) * (1.0f / (float)DC_);
    float inv = exp2f(-13.287712379549449f * ex);
    float s, c;
    sincosf((float)l * inv, &s, &c);
    g_rsin[l * DC_ + d] = s;
    g_rcos[l * DC_ + d] = c;
}

// ---------------- fused RoPE (table lookup) + partial kvsum ---------------
__global__ __launch_bounds__(256) void rope_kernel(const float* __restrict__ kv_c) {
    const int b = blockIdx.x, lb = blockIdx.y;
    const int d = threadIdx.x;
    float s0 = 0.f, s1 = 0.f;
#pragma unroll 4
    for (int l = lb * 64; l < lb * 64 + 64; l++) {
        const long base = ((long)b * L_ + l) * DC_;
        const int tbase = l * DC_ + d;
        float x0 = kv_c[base + d];
        float x1 = kv_c[base + d + 256];
        float sn0 = g_rsin[tbase],       c0 = g_rcos[tbase];
        float sn1 = g_rsin[tbase + 256], c1 = g_rcos[tbase + 256];
        float v0 = x0 * c0 - x1 * sn0;
        float v1 = x1 * c1 + x0 * sn1;
        g_kv[base + d] = v0;
        g_kv[base + d + 256] = v1;
        s0 += v0;
        s1 += v1;
    }
    g_kvp[(lb * B_ + b) * DC_ + d] = s0;
    g_kvp[(lb * B_ + b) * DC_ + d + 256] = s1;
}

__global__ __launch_bounds__(256) void kvred_kernel() {
    const int i = blockIdx.x * 256 + threadIdx.x;
    float s = 0.f;
#pragma unroll
    for (int lb = 0; lb < 8; lb++) s += g_kvp[lb * (B_ * DC_) + i];
    g_kvsum[i] = s;
}

// ---------------- scores[b,h,d] = kvsum[b,d] * sum_r qr[b,h,r]*Wkr[h,d,r] -
__global__ __launch_bounds__(256) void scores_kernel(const float* __restrict__ Wkr) {
    const int h = blockIdx.x;
    __shared__ __align__(16) float qs[B_][R_ + 4];
    __shared__ __align__(16) float ws[64][R_ + 4];
    const int tid = threadIdx.x;
    const int tcol = tid % 16;
    const int trow = tid / 16;

#pragma unroll
    for (int i = 0; i < 16; i++) {
        int idx = tid + i * 256;
        int b = idx >> 6, r = idx & 63;
        qs[b][r] = g_qr[((long)b * H_ + h) * R_ + r];
    }

    for (int d0 = 0; d0 < DC_; d0 += 64) {
        __syncthreads();
#pragma unroll
        for (int i = 0; i < 16; i++) {
            int idx = tid + i * 256;
            int dd = idx >> 6, r = idx & 63;
            ws[dd][r] = Wkr[((long)h * DC_ + d0 + dd) * R_ + r];
        }
        __syncthreads();
        float acc[4][4];
#pragma unroll
        for (int i = 0; i < 4; i++)
#pragma unroll
            for (int j = 0; j < 4; j++) acc[i][j] = 0.f;
#pragma unroll 8
        for (int r = 0; r < R_; r++) {
            float a[4], bv[4];
#pragma unroll
            for (int i = 0; i < 4; i++) a[i] = qs[trow * 4 + i][r];
#pragma unroll
            for (int j = 0; j < 4; j++) bv[j] = ws[tcol * 4 + j][r];
#pragma unroll
            for (int i = 0; i < 4; i++)
#pragma unroll
                for (int j = 0; j < 4; j++) acc[i][j] += a[i] * bv[j];
        }
#pragma unroll
        for (int i = 0; i < 4; i++) {
            int b = trow * 4 + i;
#pragma unroll
            for (int j = 0; j < 4; j++) {
                int d = d0 + tcol * 4 + j;
                g_scores[((long)b * H_ + h) * DC_ + d] = acc[i][j] * g_kvsum[b * DC_ + d];
            }
        }
    }
}

// ---------------- softmax, then subtract uniform mode 1/512 ---------------
__global__ __launch_bounds__(128) void softmax_kernel() {
    const int bh = blockIdx.x;
    float* p = g_scores + (long)bh * DC_;
    const int tid = threadIdx.x;
    __shared__ float red[128];
    float v[4];
    float mx = -1e30f;
#pragma unroll
    for (int i = 0; i < 4; i++) {
        v[i] = p[tid + i * 128];
        mx = fmaxf(mx, v[i]);
    }
    red[tid] = mx;
    __syncthreads();
    for (int s = 64; s > 0; s >>= 1) {
        if (tid < s) red[tid] = fmaxf(red[tid], red[tid + s]);
        __syncthreads();
    }
    mx = red[0];
    __syncthreads();
    float sum = 0.f;
#pragma unroll
    for (int i = 0; i < 4; i++) {
        v[i] = expf(v[i] - mx);
        sum += v[i];
    }
    red[tid] = sum;
    __syncthreads();
    for (int s = 64; s > 0; s >>= 1) {
        if (tid < s) red[tid] += red[tid + s];
        __syncthreads();
    }
    float invs = 1.0f / red[0];
#pragma unroll
    for (int i = 0; i < 4; i++)
        p[tid + i * 128] = v[i] * invs - (1.0f / 512.0f);
}

// ---------------- generic split-K reduce ----------------------------------
__global__ __launch_bounds__(256) void reduceN_kernel(float* __restrict__ dst,
                                                      const float* __restrict__ src,
                                                      int parts, long stride) {
    const long i = (long)blockIdx.x * 256 + threadIdx.x;
    float s = 0.f;
    for (int p = 0; p < parts; p++) s += src[(long)p * stride + i];
    dst[i] = s;
}

// ---------------- launch --------------------------------------------------
extern "C" void kernel_launch(void* const* d_in, const int* in_sizes, int n_in,
                              void* d_out, int out_size) {
    const float* hidden_q   = (const float*)d_in[0];
    const float* kv_c       = (const float*)d_in[1];
    const float* q_proj_w   = (const float*)d_in[2];
    const float* w_kc_q     = (const float*)d_in[3];
    const float* w_kc_kv    = (const float*)d_in[4];
    const float* W_qr       = (const float*)d_in[5];
    const float* W_kr       = (const float*)d_in[6];
    const float* out_proj_w = (const float*)d_in[7];
    float* out = (float*)d_out;

    float *qhk, *Ah, *qr, *kvsum, *scores, *ctx, *ctxlat, *part, *kv;
    cudaGetSymbolAddress((void**)&qhk,    g_qhk);
    cudaGetSymbolAddress((void**)&Ah,     g_Ah);
    cudaGetSymbolAddress((void**)&qr,     g_qr);
    cudaGetSymbolAddress((void**)&kv,     g_kv);
    cudaGetSymbolAddress((void**)&kvsum,  g_kvsum);
    cudaGetSymbolAddress((void**)&scores, g_scores);
    cudaGetSymbolAddress((void**)&ctx,    g_ctx);
    cudaGetSymbolAddress((void**)&ctxlat, g_ctxlat);
    cudaGetSymbolAddress((void**)&part,   g_part);

    // smem sizes (2 stages)
    const int smQP = 2 * stage_bytes(2, 4, false, false);  // qproj  56320
    const int smAH = 2 * stage_bytes(4, 2, true,  false);  // A_h    38912
    const int smQR = 2 * stage_bytes(2, 2, true,  false);  // qr     28672
    const int smCX = 2 * stage_bytes(4, 2, true,  true);   // ctx    59392
    const int smCL = 2 * stage_bytes(2, 4, false, true);   // ctxlat 61440
    cudaFuncSetAttribute(mgemm<2, 4, false, false, false>,
                         cudaFuncAttributeMaxDynamicSharedMemorySize, smQP);
    cudaFuncSetAttribute(mgemm<4, 2, true, true, true>,
                         cudaFuncAttributeMaxDynamicSharedMemorySize, smCX);
    cudaFuncSetAttribute(mgemm<2, 4, false, false, true>,
                         cudaFuncAttributeMaxDynamicSharedMemorySize, smCL);

    rope_tab_kernel<<<L_, 512>>>();
    rope_kernel<<<dim3(B_, 8), 256>>>(kv_c);
    kvred_kernel<<<(B_ * DC_) / 256, 256>>>();

    // q_hk = hidden_q @ q_proj_w^T  [64 x 16384], BN=128, split-K x4, 2-MMA
    mgemm<2, 4, false, false, false><<<dim3(128, 1, 4), 256, smQP>>>(
        hidden_q, q_proj_w, part, (const float*)0, 0.f, 0,
        512, 0, 0, 0, DQ_, DQ_, H_ * KH_,
        4, 512L, 512L, (long)B_ * H_ * KH_);
    reduceN_kernel<<<(B_ * H_ * KH_) / 256, 256>>>(qhk, part, 4, (long)B_ * H_ * KH_);

    // A_h = w_kc_q[h] @ W_qr[h]  (BM=128; trans B)  K split x4, 2-MMA
    mgemm<4, 2, true, false, false><<<dim3(1, 1, H_ * 4), 256, smAH>>>(
        w_kc_q, W_qr, part, (const float*)0, 0.f, 0,
        384, (long)KH_ * DCQ_, (long)DCQ_ * R_, (long)KH_ * R_,
        DCQ_, R_, R_,
        4, 384L, 384L * R_, (long)H_ * KH_ * R_);
    reduceN_kernel<<<(H_ * KH_ * R_) / 256, 256>>>(Ah, part, 4, (long)H_ * KH_ * R_);

    // q_r = q_hk[:,h,:] @ A_h  (trans B)  [64 x 64] x128, 2-MMA
    mgemm<2, 2, true, false, false><<<dim3(1, 1, H_), 256, smQR>>>(
        qhk, Ah, qr, (const float*)0, 0.f, 0,
        KH_, (long)KH_, (long)KH_ * R_, (long)R_, H_ * KH_, R_, H_ * R_,
        1, 0, 0, 0);

    scores_kernel<<<H_, 256>>>(W_kr);
    softmax_kernel<<<B_ * H_, 128>>>();

    // ctx = (attn - 1/512) @ kv + kvsum/512  (BM=128; trans B, bias), 3-MMA
    mgemm<4, 2, true, true, true><<<dim3(DC_ / 64, 1, B_), 256, smCX>>>(
        scores, kv, ctx, kvsum, 1.0f / 512.0f, (long)DC_,
        DC_, (long)H_ * DC_, (long)L_ * DC_, (long)H_ * DC_,
        DC_, DC_, DC_,
        1, 0, 0, 0);

    // ctxlat = ctx[:,h,:] @ w_kc_kv[h]^T  BN=128, [64 x 128] x128, 3-MMA
    mgemm<2, 4, false, false, true><<<dim3(1, 1, H_), 256, smCL>>>(
        ctx, w_kc_kv, ctxlat, (const float*)0, 0.f, 0,
        DC_, (long)DC_, (long)KH_ * DC_, (long)KH_, H_ * DC_, DC_, H_ * KH_,
        1, 0, 0, 0);

    // out = ctxlat @ out_proj_w^T  BN=128, K=16384, split-K x16, 3-MMA
    mgemm<2, 4, false, false, true><<<dim3(DQ_ / 128, 1, 16), 256, smCL>>>(
        ctxlat, out_proj_w, part, (const float*)0, 0.f, 0,
        1024, 0, 0, 0, H_ * KH_, H_ * KH_, DQ_,
        16, 1024L, 1024L, (long)B_ * DQ_);
    reduceN_kernel<<<(B_ * DQ_) / 256, 256>>>(out, part, 16, (long)B_ * DQ_);
}

// round 13
// speedup vs baseline: 1.3724x; 1.3724x over previous
#include <cuda_runtime.h>
#include <cuda_bf16.h>
#include <math.h>
#include <stdint.h>

#define B_   64
#define L_   512
#define DQ_  2048
#define H_   128
#define KH_  128
#define DC_  512
#define DCQ_ 1536
#define R_   64

// ---------------- scratch (device globals; no allocation allowed) ----------
__device__ float g_qhk[B_ * H_ * KH_];
__device__ float g_Ah[H_ * KH_ * R_];
__device__ float g_qr[B_ * H_ * R_];
__device__ float g_kv[B_ * L_ * DC_];
__device__ float g_kvp[8 * B_ * DC_];
__device__ float g_kvsum[B_ * DC_];
__device__ float g_scores[B_ * H_ * DC_];
__device__ float g_ctx[B_ * H_ * DC_];
__device__ float g_ctxlat[B_ * H_ * KH_];
__device__ float g_part[4 * 1048576];
__device__ float g_rsin[L_ * DC_];
__device__ float g_rcos[L_ * DC_];

// ---------------- bf16 helpers ---------------------------------------------
__device__ __forceinline__ void bsplit4(float4 v, uint2& hi, uint2& lo) {
    uint32_t h01, h23, l01, l23;
    asm("cvt.rn.bf16x2.f32 %0, %1, %2;" : "=r"(h01) : "f"(v.y), "f"(v.x));
    asm("cvt.rn.bf16x2.f32 %0, %1, %2;" : "=r"(h23) : "f"(v.w), "f"(v.z));
    float r0 = v.x - __uint_as_float(h01 << 16);
    float r1 = v.y - __uint_as_float(h01 & 0xFFFF0000u);
    float r2 = v.z - __uint_as_float(h23 << 16);
    float r3 = v.w - __uint_as_float(h23 & 0xFFFF0000u);
    asm("cvt.rn.bf16x2.f32 %0, %1, %2;" : "=r"(l01) : "f"(r1), "f"(r0));
    asm("cvt.rn.bf16x2.f32 %0, %1, %2;" : "=r"(l23) : "f"(r3), "f"(r2));
    hi.x = h01; hi.y = h23; lo.x = l01; lo.y = l23;
}
__device__ __forceinline__ void bhi4(float4 v, uint2& hi) {
    uint32_t h01, h23;
    asm("cvt.rn.bf16x2.f32 %0, %1, %2;" : "=r"(h01) : "f"(v.y), "f"(v.x));
    asm("cvt.rn.bf16x2.f32 %0, %1, %2;" : "=r"(h23) : "f"(v.w), "f"(v.z));
    hi.x = h01; hi.y = h23;
}

#define LDMX4(r, a)                                                           \
    asm volatile("ldmatrix.sync.aligned.m8n8.x4.shared.b16 {%0,%1,%2,%3}, [%4];" \
                 : "=r"((r)[0]), "=r"((r)[1]), "=r"((r)[2]), "=r"((r)[3])     \
                 : "r"(a))
#define LDMX2(r, a)                                                           \
    asm volatile("ldmatrix.sync.aligned.m8n8.x2.shared.b16 {%0,%1}, [%2];"    \
                 : "=r"((r)[0]), "=r"((r)[1]) : "r"(a))
#define LDMX2T(r, a)                                                          \
    asm volatile("ldmatrix.sync.aligned.m8n8.x2.trans.shared.b16 {%0,%1}, [%2];" \
                 : "=r"((r)[0]), "=r"((r)[1]) : "r"(a))

#define MMAB(d, a, b)                                                         \
    asm volatile(                                                             \
        "mma.sync.aligned.m16n8k16.row.col.f32.bf16.bf16.f32 "                \
        "{%0,%1,%2,%3}, {%4,%5,%6,%7}, {%8,%9}, {%0,%1,%2,%3};"               \
        : "+f"((d)[0]), "+f"((d)[1]), "+f"((d)[2]), "+f"((d)[3])              \
        : "r"((a)[0]), "r"((a)[1]), "r"((a)[2]), "r"((a)[3]),                 \
          "r"((b)[0]), "r"((b)[1]))

// ---------------- split-bf16 mma.sync GEMM  (BM=32*MI, BN=32*NJ, BK=32) ----
// C[m,n] = sum_k A[m,k] * B[n,k].  TRANSB: B source [K,N] row-major.
// ALO=true : 3 MMAs/k16 (ah*bh + ah*bl + al*bh)  — full precision path.
// ALO=false: 2 MMAs/k16 (ah*bh + ah*bl), no A-lo plane — q-path only.
// 2-stage SMEM double buffer, prefetch distance 2. Split-K via blockIdx.z.
template <int MI, int NJ, bool TRANSB, bool BIAS, bool ALO>
__global__ __launch_bounds__(256)
void mgemm(const float* __restrict__ A, const float* __restrict__ Bm,
           float* __restrict__ C, const float* __restrict__ bias,
           float bscale, long sBiasz, int Kd,
           long sAz, long sBz, long sCz, int lda, int ldb, int ldc,
           int nspl, long sAsp, long sBsp, long sCsp) {
    constexpr int BM = 32 * MI, BN = 32 * NJ;
    constexpr int PA = 80;
    constexpr int PBT = BN * 2 + 16;
    constexpr int ASZ = BM * PA;
    constexpr int BSZ = TRANSB ? 32 * PBT : BN * PA;
    constexpr int APL = ALO ? 2 : 1;
    constexpr int A_HI = 0, A_LO = ASZ;
    constexpr int B_HI = APL * ASZ, B_LO = APL * ASZ + BSZ;
    constexpr int STAGE = APL * ASZ + 2 * BSZ;
    constexpr int N4 = BN / 4;
    constexpr int KSTEP_T = 256 / N4;

    extern __shared__ __align__(16) char sm[];

    const int tid = threadIdx.x, lane = tid & 31, wid = tid >> 5;
    const int wm = wid >> 2, wn = wid & 3;
    const int n0 = blockIdx.x * BN, m0 = blockIdx.y * BM;
    int bz = blockIdx.z, sp = 0;
    if (nspl > 1) { sp = bz % nspl; bz /= nspl; }

    const float* Ab = A + (long)bz * sAz + (long)sp * sAsp + (long)m0 * lda;
    const float* Bb = (TRANSB ? (Bm + (long)bz * sBz + (long)sp * sBsp + n0)
                              : (Bm + (long)bz * sBz + (long)sp * sBsp +
                                 (long)n0 * ldb));
    float* Cb = C + (long)bz * sCz + (long)sp * sCsp;

    float acc[MI][NJ][4];
#pragma unroll
    for (int mi = 0; mi < MI; mi++)
#pragma unroll
        for (int nj = 0; nj < NJ; nj++)
#pragma unroll
            for (int e = 0; e < 4; e++) acc[mi][nj][e] = 0.f;

    const int a_row0 = tid >> 3, a_c4 = tid & 7;
    const int bt_n4 = tid & (N4 - 1), bt_k0 = tid / N4;

    const int lane7 = lane & 7, laneb = (lane >> 3) & 1, lanet = lane >> 4;
    uint32_t aoff[MI][2], boff[NJ][2];
#pragma unroll
    for (int mi = 0; mi < MI; mi++)
#pragma unroll
        for (int s = 0; s < 2; s++)
            aoff[mi][s] = (uint32_t)((wm * (16 * MI) + mi * 16 + lane7 + laneb * 8) * PA +
                                     (s * 16 + lanet * 8) * 2);
#pragma unroll
    for (int nj = 0; nj < NJ; nj++)
#pragma unroll
        for (int s = 0; s < 2; s++) {
            if (TRANSB)
                boff[nj][s] = (uint32_t)((s * 16 + laneb * 8 + lane7) * PBT +
                                         (wn * (8 * NJ) + nj * 8) * 2);
            else
                boff[nj][s] = (uint32_t)((wn * (8 * NJ) + nj * 8 + lane7) * PA +
                                         (s * 16 + laneb * 8) * 2);
        }
    const uint32_t smb = (uint32_t)__cvta_generic_to_shared(sm);

    float4 pa[MI], pb[NJ];
    const int nch = Kd >> 5;

#define LDG_CH(k0v)                                                           \
    do {                                                                      \
        _Pragma("unroll")                                                     \
        for (int i = 0; i < MI; i++)                                          \
            pa[i] = *(const float4*)(Ab + (long)(a_row0 + i * 32) * lda +     \
                                     (k0v) + (a_c4 << 2));                    \
        if (!TRANSB) {                                                        \
            _Pragma("unroll")                                                 \
            for (int i = 0; i < NJ; i++)                                      \
                pb[i] = *(const float4*)(Bb + (long)(a_row0 + i * 32) * ldb + \
                                         (k0v) + (a_c4 << 2));                \
        } else {                                                              \
            _Pragma("unroll")                                                 \
            for (int i = 0; i < NJ; i++)                                      \
                pb[i] = *(const float4*)(Bb +                                 \
                         (long)((k0v) + bt_k0 + i * KSTEP_T) * ldb +          \
                         (bt_n4 << 2));                                       \
        }                                                                     \
    } while (0)

#define STS_CH(buf)                                                           \
    do {                                                                      \
        char* st = sm + (buf) * STAGE;                                        \
        _Pragma("unroll")                                                     \
        for (int i = 0; i < MI; i++) {                                        \
            int off = (a_row0 + i * 32) * PA + a_c4 * 8;                      \
            if (ALO) {                                                        \
                uint2 hi, lo;                                                 \
                bsplit4(pa[i], hi, lo);                                       \
                *(uint2*)(st + A_HI + off) = hi;                              \
                *(uint2*)(st + A_LO + off) = lo;                              \
            } else {                                                          \
                uint2 hi;                                                     \
                bhi4(pa[i], hi);                                              \
                *(uint2*)(st + A_HI + off) = hi;                              \
            }                                                                 \
        }                                                                     \
        _Pragma("unroll")                                                     \
        for (int i = 0; i < NJ; i++) {                                        \
            uint2 hi, lo;                                                     \
            bsplit4(pb[i], hi, lo);                                           \
            int off = TRANSB ? ((bt_k0 + i * KSTEP_T) * PBT + bt_n4 * 8)      \
                             : ((a_row0 + i * 32) * PA + a_c4 * 8);           \
            *(uint2*)(st + B_HI + off) = hi;                                  \
            *(uint2*)(st + B_LO + off) = lo;                                  \
        }                                                                     \
    } while (0)

    LDG_CH(0);
    STS_CH(0);
    if (nch > 1) LDG_CH(32);
    __syncthreads();

    for (int ch = 0; ch < nch; ch++) {
        const int cur = ch & 1;
        if (ch + 1 < nch) {
            STS_CH(1 - cur);
            if (ch + 2 < nch) LDG_CH((ch + 2) << 5);
        }
        const uint32_t sb = smb + cur * STAGE;
#pragma unroll
        for (int s = 0; s < 2; s++) {
            uint32_t ah[MI][4], al[ALO ? MI : 1][4], bh[NJ][2], bl[NJ][2];
#pragma unroll
            for (int mi = 0; mi < MI; mi++) {
                LDMX4(ah[mi], sb + A_HI + aoff[mi][s]);
                if (ALO) LDMX4(al[mi], sb + A_LO + aoff[mi][s]);
            }
#pragma unroll
            for (int nj = 0; nj < NJ; nj++) {
                if (TRANSB) {
                    LDMX2T(bh[nj], sb + B_HI + boff[nj][s]);
                    LDMX2T(bl[nj], sb + B_LO + boff[nj][s]);
                } else {
                    LDMX2(bh[nj], sb + B_HI + boff[nj][s]);
                    LDMX2(bl[nj], sb + B_LO + boff[nj][s]);
                }
            }
#pragma unroll
            for (int mi = 0; mi < MI; mi++)
#pragma unroll
                for (int nj = 0; nj < NJ; nj++) {
                    MMAB(acc[mi][nj], ah[mi], bh[nj]);
                    MMAB(acc[mi][nj], ah[mi], bl[nj]);
                    if (ALO) MMAB(acc[mi][nj], al[mi], bh[nj]);
                }
        }
        __syncthreads();
    }
#undef LDG_CH
#undef STS_CH

    const float* bias_b = BIAS ? (bias + (long)bz * sBiasz) : (const float*)0;
#pragma unroll
    for (int mi = 0; mi < MI; mi++)
#pragma unroll
        for (int nj = 0; nj < NJ; nj++) {
            int r = m0 + wm * (16 * MI) + mi * 16 + (lane >> 2);
            int c = n0 + wn * (8 * NJ) + nj * 8 + ((lane & 3) << 1);
            float2 v0 = make_float2(acc[mi][nj][0], acc[mi][nj][1]);
            float2 v1 = make_float2(acc[mi][nj][2], acc[mi][nj][3]);
            if (BIAS) {
                float b0 = bias_b[c] * bscale, b1 = bias_b[c + 1] * bscale;
                v0.x += b0; v0.y += b1; v1.x += b0; v1.y += b1;
            }
            *(float2*)&Cb[(long)r * ldc + c] = v0;
            *(float2*)&Cb[(long)(r + 8) * ldc + c] = v1;
        }
}

static inline int stage_bytes(int MI, int NJ, bool TB, bool ALO) {
    int asz = 32 * MI * 80;
    int bsz = TB ? 32 * (32 * NJ * 2 + 16) : 32 * NJ * 80;
    return (ALO ? 2 : 1) * asz + 2 * bsz;
}

// ---------------- RoPE table: sin/cos per (l, d) once ---------------------
__global__ __launch_bounds__(512) void rope_tab_kernel() {
    const int l = blockIdx.x;
    const int d = threadIdx.x;
    float ex = (float)(d & ~1) * (1.0f / (float)DC_);
    float inv = exp2f(-13.287712379549449f * ex);
    float s, c;
    sincosf((float)l * inv, &s, &c);
    g_rsin[l * DC_ + d] = s;
    g_rcos[l * DC_ + d] = c;
}

// ---------------- fused RoPE (table lookup) + partial kvsum ---------------
__global__ __launch_bounds__(256) void rope_kernel(const float* __restrict__ kv_c) {
    const int b = blockIdx.x, lb = blockIdx.y;
    const int d = threadIdx.x;
    float s0 = 0.f, s1 = 0.f;
#pragma unroll 4
    for (int l = lb * 64; l < lb * 64 + 64; l++) {
        const long base = ((long)b * L_ + l) * DC_;
        const int tbase = l * DC_ + d;
        float x0 = kv_c[base + d];
        float x1 = kv_c[base + d + 256];
        float sn0 = g_rsin[tbase],       c0 = g_rcos[tbase];
        float sn1 = g_rsin[tbase + 256], c1 = g_rcos[tbase + 256];
        float v0 = x0 * c0 - x1 * sn0;
        float v1 = x1 * c1 + x0 * sn1;
        g_kv[base + d] = v0;
        g_kv[base + d + 256] = v1;
        s0 += v0;
        s1 += v1;
    }
    g_kvp[(lb * B_ + b) * DC_ + d] = s0;
    g_kvp[(lb * B_ + b) * DC_ + d + 256] = s1;
}

__global__ __launch_bounds__(256) void kvred_kernel() {
    const int i = blockIdx.x * 256 + threadIdx.x;
    float s = 0.f;
#pragma unroll
    for (int lb = 0; lb < 8; lb++) s += g_kvp[lb * (B_ * DC_) + i];
    g_kvsum[i] = s;
}

// ---------------- scores[b,h,d] = kvsum[b,d] * sum_r qr[b,h,r]*Wkr[h,d,r] -
__global__ __launch_bounds__(256) void scores_kernel(const float* __restrict__ Wkr) {
    const int h = blockIdx.x;
    __shared__ __align__(16) float qs[B_][R_ + 4];
    __shared__ __align__(16) float ws[64][R_ + 4];
    const int tid = threadIdx.x;
    const int tcol = tid % 16;
    const int trow = tid / 16;

#pragma unroll
    for (int i = 0; i < 16; i++) {
        int idx = tid + i * 256;
        int b = idx >> 6, r = idx & 63;
        qs[b][r] = g_qr[((long)b * H_ + h) * R_ + r];
    }

    for (int d0 = 0; d0 < DC_; d0 += 64) {
        __syncthreads();
#pragma unroll
        for (int i = 0; i < 16; i++) {
            int idx = tid + i * 256;
            int dd = idx >> 6, r = idx & 63;
            ws[dd][r] = Wkr[((long)h * DC_ + d0 + dd) * R_ + r];
        }
        __syncthreads();
        float acc[4][4];
#pragma unroll
        for (int i = 0; i < 4; i++)
#pragma unroll
            for (int j = 0; j < 4; j++) acc[i][j] = 0.f;
#pragma unroll 8
        for (int r = 0; r < R_; r++) {
            float a[4], bv[4];
#pragma unroll
            for (int i = 0; i < 4; i++) a[i] = qs[trow * 4 + i][r];
#pragma unroll
            for (int j = 0; j < 4; j++) bv[j] = ws[tcol * 4 + j][r];
#pragma unroll
            for (int i = 0; i < 4; i++)
#pragma unroll
                for (int j = 0; j < 4; j++) acc[i][j] += a[i] * bv[j];
        }
#pragma unroll
        for (int i = 0; i < 4; i++) {
            int b = trow * 4 + i;
#pragma unroll
            for (int j = 0; j < 4; j++) {
                int d = d0 + tcol * 4 + j;
                g_scores[((long)b * H_ + h) * DC_ + d] = acc[i][j] * g_kvsum[b * DC_ + d];
            }
        }
    }
}

// ---------------- softmax, then subtract uniform mode 1/512 ---------------
__global__ __launch_bounds__(128) void softmax_kernel() {
    const int bh = blockIdx.x;
    float* p = g_scores + (long)bh * DC_;
    const int tid = threadIdx.x;
    __shared__ float red[128];
    float v[4];
    float mx = -1e30f;
#pragma unroll
    for (int i = 0; i < 4; i++) {
        v[i] = p[tid + i * 128];
        mx = fmaxf(mx, v[i]);
    }
    red[tid] = mx;
    __syncthreads();
    for (int s = 64; s > 0; s >>= 1) {
        if (tid < s) red[tid] = fmaxf(red[tid], red[tid + s]);
        __syncthreads();
    }
    mx = red[0];
    __syncthreads();
    float sum = 0.f;
#pragma unroll
    for (int i = 0; i < 4; i++) {
        v[i] = expf(v[i] - mx);
        sum += v[i];
    }
    red[tid] = sum;
    __syncthreads();
    for (int s = 64; s > 0; s >>= 1) {
        if (tid < s) red[tid] += red[tid + s];
        __syncthreads();
    }
    float invs = 1.0f / red[0];
#pragma unroll
    for (int i = 0; i < 4; i++)
        p[tid + i * 128] = v[i] * invs - (1.0f / 512.0f);
}

// ---------------- generic split-K reduce ----------------------------------
__global__ __launch_bounds__(256) void reduceN_kernel(float* __restrict__ dst,
                                                      const float* __restrict__ src,
                                                      int parts, long stride) {
    const long i = (long)blockIdx.x * 256 + threadIdx.x;
    float s = 0.f;
    for (int p = 0; p < parts; p++) s += src[(long)p * stride + i];
    dst[i] = s;
}

// ---------------- launch --------------------------------------------------
extern "C" void kernel_launch(void* const* d_in, const int* in_sizes, int n_in,
                              void* d_out, int out_size) {
    const float* hidden_q   = (const float*)d_in[0];
    const float* kv_c       = (const float*)d_in[1];
    const float* q_proj_w   = (const float*)d_in[2];
    const float* w_kc_q     = (const float*)d_in[3];
    const float* w_kc_kv    = (const float*)d_in[4];
    const float* W_qr       = (const float*)d_in[5];
    const float* W_kr       = (const float*)d_in[6];
    const float* out_proj_w = (const float*)d_in[7];
    float* out = (float*)d_out;

    float *qhk, *Ah, *qr, *kvsum, *scores, *ctx, *ctxlat, *part, *kv;
    cudaGetSymbolAddress((void**)&qhk,    g_qhk);
    cudaGetSymbolAddress((void**)&Ah,     g_Ah);
    cudaGetSymbolAddress((void**)&qr,     g_qr);
    cudaGetSymbolAddress((void**)&kv,     g_kv);
    cudaGetSymbolAddress((void**)&kvsum,  g_kvsum);
    cudaGetSymbolAddress((void**)&scores, g_scores);
    cudaGetSymbolAddress((void**)&ctx,    g_ctx);
    cudaGetSymbolAddress((void**)&ctxlat, g_ctxlat);
    cudaGetSymbolAddress((void**)&part,   g_part);

    // smem sizes (2 stages)
    const int smQP = 2 * stage_bytes(2, 2, false, false);  // qproj  30720
    const int smAH = 2 * stage_bytes(4, 2, true,  false);  // A_h    38912
    const int smQR = 2 * stage_bytes(2, 2, true,  false);  // qr     28672
    const int smCX = 2 * stage_bytes(4, 2, true,  true);   // ctx    59392
    const int smCL = 2 * stage_bytes(2, 2, false, true);   // ctxlat 40960
    cudaFuncSetAttribute(mgemm<4, 2, true, true, true>,
                         cudaFuncAttributeMaxDynamicSharedMemorySize, smCX);

    rope_tab_kernel<<<L_, 512>>>();
    rope_kernel<<<dim3(B_, 8), 256>>>(kv_c);
    kvred_kernel<<<(B_ * DC_) / 256, 256>>>();

    // q_hk = hidden_q @ q_proj_w^T  [64 x 16384], split-K x4, 2-MMA
    mgemm<2, 2, false, false, false><<<dim3(256, 1, 4), 256, smQP>>>(
        hidden_q, q_proj_w, part, (const float*)0, 0.f, 0,
        512, 0, 0, 0, DQ_, DQ_, H_ * KH_,
        4, 512L, 512L, (long)B_ * H_ * KH_);
    reduceN_kernel<<<(B_ * H_ * KH_) / 256, 256>>>(qhk, part, 4, (long)B_ * H_ * KH_);

    // A_h = w_kc_q[h] @ W_qr[h]  (BM=128; trans B)  K split x4, 2-MMA
    mgemm<4, 2, true, false, false><<<dim3(1, 1, H_ * 4), 256, smAH>>>(
        w_kc_q, W_qr, part, (const float*)0, 0.f, 0,
        384, (long)KH_ * DCQ_, (long)DCQ_ * R_, (long)KH_ * R_,
        DCQ_, R_, R_,
        4, 384L, 384L * R_, (long)H_ * KH_ * R_);
    reduceN_kernel<<<(H_ * KH_ * R_) / 256, 256>>>(Ah, part, 4, (long)H_ * KH_ * R_);

    // q_r = q_hk[:,h,:] @ A_h  (trans B)  [64 x 64] x128, 2-MMA
    mgemm<2, 2, true, false, false><<<dim3(1, 1, H_), 256, smQR>>>(
        qhk, Ah, qr, (const float*)0, 0.f, 0,
        KH_, (long)KH_, (long)KH_ * R_, (long)R_, H_ * KH_, R_, H_ * R_,
        1, 0, 0, 0);

    scores_kernel<<<H_, 256>>>(W_kr);
    softmax_kernel<<<B_ * H_, 128>>>();

    // ctx = (attn - 1/512) @ kv + kvsum/512  (BM=128; trans B, bias), 3-MMA
    mgemm<4, 2, true, true, true><<<dim3(DC_ / 64, 1, B_), 256, smCX>>>(
        scores, kv, ctx, kvsum, 1.0f / 512.0f, (long)DC_,
        DC_, (long)H_ * DC_, (long)L_ * DC_, (long)H_ * DC_,
        DC_, DC_, DC_,
        1, 0, 0, 0);

    // ctxlat = ctx[:,h,:] @ w_kc_kv[h]^T  [64 x 128] x128, 3-MMA
    mgemm<2, 2, false, false, true><<<dim3(KH_ / 64, 1, H_), 256, smCL>>>(
        ctx, w_kc_kv, ctxlat, (const float*)0, 0.f, 0,
        DC_, (long)DC_, (long)KH_ * DC_, (long)KH_, H_ * DC_, DC_, H_ * KH_,
        1, 0, 0, 0);

    // out = ctxlat @ out_proj_w^T  K=16384, split-K x16, 3-MMA
    mgemm<2, 2, false, false, true><<<dim3(DQ_ / 64, 1, 16), 256, smCL>>>(
        ctxlat, out_proj_w, part, (const float*)0, 0.f, 0,
        1024, 0, 0, 0, H_ * KH_, H_ * KH_, DQ_,
        16, 1024L, 1024L, (long)B_ * DQ_);
    reduceN_kernel<<<(B_ * DQ_) / 256, 256>>>(out, part, 16, (long)B_ * DQ_);
}

// round 14
// speedup vs baseline: 1.3937x; 1.0156x over previous
#include <cuda_runtime.h>
#include <cuda_bf16.h>
#include <math.h>
#include <stdint.h>

#define B_   64
#define L_   512
#define DQ_  2048
#define H_   128
#define KH_  128
#define DC_  512
#define DCQ_ 1536
#define R_   64

// ---------------- scratch (device globals; no allocation allowed) ----------
__device__ float g_qhk[B_ * H_ * KH_];
__device__ float g_Ah[H_ * KH_ * R_];
__device__ float g_qr[B_ * H_ * R_];
__device__ float g_kv[B_ * L_ * DC_];
__device__ float g_kvp[8 * B_ * DC_];
__device__ float g_kvsum[B_ * DC_];
__device__ float g_scores[B_ * H_ * DC_];
__device__ float g_ctx[B_ * H_ * DC_];
__device__ float g_ctxlat[B_ * H_ * KH_];
__device__ float g_part[4 * 1048576];
__device__ float g_rsin[L_ * DC_];
__device__ float g_rcos[L_ * DC_];

// ---------------- bf16 helpers ---------------------------------------------
__device__ __forceinline__ void bsplit4(float4 v, uint2& hi, uint2& lo) {
    uint32_t h01, h23, l01, l23;
    asm("cvt.rn.bf16x2.f32 %0, %1, %2;" : "=r"(h01) : "f"(v.y), "f"(v.x));
    asm("cvt.rn.bf16x2.f32 %0, %1, %2;" : "=r"(h23) : "f"(v.w), "f"(v.z));
    float r0 = v.x - __uint_as_float(h01 << 16);
    float r1 = v.y - __uint_as_float(h01 & 0xFFFF0000u);
    float r2 = v.z - __uint_as_float(h23 << 16);
    float r3 = v.w - __uint_as_float(h23 & 0xFFFF0000u);
    asm("cvt.rn.bf16x2.f32 %0, %1, %2;" : "=r"(l01) : "f"(r1), "f"(r0));
    asm("cvt.rn.bf16x2.f32 %0, %1, %2;" : "=r"(l23) : "f"(r3), "f"(r2));
    hi.x = h01; hi.y = h23; lo.x = l01; lo.y = l23;
}
__device__ __forceinline__ void bhi4(float4 v, uint2& hi) {
    uint32_t h01, h23;
    asm("cvt.rn.bf16x2.f32 %0, %1, %2;" : "=r"(h01) : "f"(v.y), "f"(v.x));
    asm("cvt.rn.bf16x2.f32 %0, %1, %2;" : "=r"(h23) : "f"(v.w), "f"(v.z));
    hi.x = h01; hi.y = h23;
}

#define LDMX4(r, a)                                                           \
    asm volatile("ldmatrix.sync.aligned.m8n8.x4.shared.b16 {%0,%1,%2,%3}, [%4];" \
                 : "=r"((r)[0]), "=r"((r)[1]), "=r"((r)[2]), "=r"((r)[3])     \
                 : "r"(a))
#define LDMX2(r, a)                                                           \
    asm volatile("ldmatrix.sync.aligned.m8n8.x2.shared.b16 {%0,%1}, [%2];"    \
                 : "=r"((r)[0]), "=r"((r)[1]) : "r"(a))
#define LDMX2T(r, a)                                                          \
    asm volatile("ldmatrix.sync.aligned.m8n8.x2.trans.shared.b16 {%0,%1}, [%2];" \
                 : "=r"((r)[0]), "=r"((r)[1]) : "r"(a))

#define MMAB(d, a, b)                                                         \
    asm volatile(                                                             \
        "mma.sync.aligned.m16n8k16.row.col.f32.bf16.bf16.f32 "                \
        "{%0,%1,%2,%3}, {%4,%5,%6,%7}, {%8,%9}, {%0,%1,%2,%3};"               \
        : "+f"((d)[0]), "+f"((d)[1]), "+f"((d)[2]), "+f"((d)[3])              \
        : "r"((a)[0]), "r"((a)[1]), "r"((a)[2]), "r"((a)[3]),                 \
          "r"((b)[0]), "r"((b)[1]))

// ---------------- split-bf16 mma.sync GEMM  (BM=32*MI, BN=32*NJ, BK=32) ----
// C[m,n] = sum_k A[m,k] * B[n,k].  TRANSB: B source [K,N] row-major.
// Per k16: ah*bh  (+ ah*bl if BLO)  (+ al*bh if ALO).
// 2-stage SMEM double buffer, prefetch distance 2. Split-K via blockIdx.z.
template <int MI, int NJ, bool TRANSB, bool BIAS, bool ALO, bool BLO>
__global__ __launch_bounds__(256)
void mgemm(const float* __restrict__ A, const float* __restrict__ Bm,
           float* __restrict__ C, const float* __restrict__ bias,
           float bscale, long sBiasz, int Kd,
           long sAz, long sBz, long sCz, int lda, int ldb, int ldc,
           int nspl, long sAsp, long sBsp, long sCsp) {
    constexpr int BM = 32 * MI, BN = 32 * NJ;
    constexpr int PA = 80;
    constexpr int PBT = BN * 2 + 16;
    constexpr int ASZ = BM * PA;
    constexpr int BSZ = TRANSB ? 32 * PBT : BN * PA;
    constexpr int APL = ALO ? 2 : 1;
    constexpr int BPL = BLO ? 2 : 1;
    constexpr int A_HI = 0, A_LO = ASZ;
    constexpr int B_HI = APL * ASZ, B_LO = APL * ASZ + BSZ;
    constexpr int STAGE = APL * ASZ + BPL * BSZ;
    constexpr int N4 = BN / 4;
    constexpr int KSTEP_T = 256 / N4;

    extern __shared__ __align__(16) char sm[];

    const int tid = threadIdx.x, lane = tid & 31, wid = tid >> 5;
    const int wm = wid >> 2, wn = wid & 3;
    const int n0 = blockIdx.x * BN, m0 = blockIdx.y * BM;
    int bz = blockIdx.z, sp = 0;
    if (nspl > 1) { sp = bz % nspl; bz /= nspl; }

    const float* Ab = A + (long)bz * sAz + (long)sp * sAsp + (long)m0 * lda;
    const float* Bb = (TRANSB ? (Bm + (long)bz * sBz + (long)sp * sBsp + n0)
                              : (Bm + (long)bz * sBz + (long)sp * sBsp +
                                 (long)n0 * ldb));
    float* Cb = C + (long)bz * sCz + (long)sp * sCsp;

    float acc[MI][NJ][4];
#pragma unroll
    for (int mi = 0; mi < MI; mi++)
#pragma unroll
        for (int nj = 0; nj < NJ; nj++)
#pragma unroll
            for (int e = 0; e < 4; e++) acc[mi][nj][e] = 0.f;

    const int a_row0 = tid >> 3, a_c4 = tid & 7;
    const int bt_n4 = tid & (N4 - 1), bt_k0 = tid / N4;

    const int lane7 = lane & 7, laneb = (lane >> 3) & 1, lanet = lane >> 4;
    uint32_t aoff[MI][2], boff[NJ][2];
#pragma unroll
    for (int mi = 0; mi < MI; mi++)
#pragma unroll
        for (int s = 0; s < 2; s++)
            aoff[mi][s] = (uint32_t)((wm * (16 * MI) + mi * 16 + lane7 + laneb * 8) * PA +
                                     (s * 16 + lanet * 8) * 2);
#pragma unroll
    for (int nj = 0; nj < NJ; nj++)
#pragma unroll
        for (int s = 0; s < 2; s++) {
            if (TRANSB)
                boff[nj][s] = (uint32_t)((s * 16 + laneb * 8 + lane7) * PBT +
                                         (wn * (8 * NJ) + nj * 8) * 2);
            else
                boff[nj][s] = (uint32_t)((wn * (8 * NJ) + nj * 8 + lane7) * PA +
                                         (s * 16 + laneb * 8) * 2);
        }
    const uint32_t smb = (uint32_t)__cvta_generic_to_shared(sm);

    float4 pa[MI], pb[NJ];
    const int nch = Kd >> 5;

#define LDG_CH(k0v)                                                           \
    do {                                                                      \
        _Pragma("unroll")                                                     \
        for (int i = 0; i < MI; i++)                                          \
            pa[i] = *(const float4*)(Ab + (long)(a_row0 + i * 32) * lda +     \
                                     (k0v) + (a_c4 << 2));                    \
        if (!TRANSB) {                                                        \
            _Pragma("unroll")                                                 \
            for (int i = 0; i < NJ; i++)                                      \
                pb[i] = *(const float4*)(Bb + (long)(a_row0 + i * 32) * ldb + \
                                         (k0v) + (a_c4 << 2));                \
        } else {                                                              \
            _Pragma("unroll")                                                 \
            for (int i = 0; i < NJ; i++)                                      \
                pb[i] = *(const float4*)(Bb +                                 \
                         (long)((k0v) + bt_k0 + i * KSTEP_T) * ldb +          \
                         (bt_n4 << 2));                                       \
        }                                                                     \
    } while (0)

#define STS_CH(buf)                                                           \
    do {                                                                      \
        char* st = sm + (buf) * STAGE;                                        \
        _Pragma("unroll")                                                     \
        for (int i = 0; i < MI; i++) {                                        \
            int off = (a_row0 + i * 32) * PA + a_c4 * 8;                      \
            if (ALO) {                                                        \
                uint2 hi, lo;                                                 \
                bsplit4(pa[i], hi, lo);                                       \
                *(uint2*)(st + A_HI + off) = hi;                              \
                *(uint2*)(st + A_LO + off) = lo;                              \
            } else {                                                          \
                uint2 hi;                                                     \
                bhi4(pa[i], hi);                                              \
                *(uint2*)(st + A_HI + off) = hi;                              \
            }                                                                 \
        }                                                                     \
        _Pragma("unroll")                                                     \
        for (int i = 0; i < NJ; i++) {                                        \
            int off = TRANSB ? ((bt_k0 + i * KSTEP_T) * PBT + bt_n4 * 8)      \
                             : ((a_row0 + i * 32) * PA + a_c4 * 8);           \
            if (BLO) {                                                        \
                uint2 hi, lo;                                                 \
                bsplit4(pb[i], hi, lo);                                       \
                *(uint2*)(st + B_HI + off) = hi;                              \
                *(uint2*)(st + B_LO + off) = lo;                              \
            } else {                                                          \
                uint2 hi;                                                     \
                bhi4(pb[i], hi);                                              \
                *(uint2*)(st + B_HI + off) = hi;                              \
            }                                                                 \
        }                                                                     \
    } while (0)

    LDG_CH(0);
    STS_CH(0);
    if (nch > 1) LDG_CH(32);
    __syncthreads();

    for (int ch = 0; ch < nch; ch++) {
        const int cur = ch & 1;
        if (ch + 1 < nch) {
            STS_CH(1 - cur);
            if (ch + 2 < nch) LDG_CH((ch + 2) << 5);
        }
        const uint32_t sb = smb + cur * STAGE;
#pragma unroll
        for (int s = 0; s < 2; s++) {
            uint32_t ah[MI][4], al[ALO ? MI : 1][4];
            uint32_t bh[NJ][2], bl[BLO ? NJ : 1][2];
#pragma unroll
            for (int mi = 0; mi < MI; mi++) {
                LDMX4(ah[mi], sb + A_HI + aoff[mi][s]);
                if (ALO) LDMX4(al[mi], sb + A_LO + aoff[mi][s]);
            }
#pragma unroll
            for (int nj = 0; nj < NJ; nj++) {
                if (TRANSB) {
                    LDMX2T(bh[nj], sb + B_HI + boff[nj][s]);
                    if (BLO) LDMX2T(bl[nj], sb + B_LO + boff[nj][s]);
                } else {
                    LDMX2(bh[nj], sb + B_HI + boff[nj][s]);
                    if (BLO) LDMX2(bl[nj], sb + B_LO + boff[nj][s]);
                }
            }
#pragma unroll
            for (int mi = 0; mi < MI; mi++)
#pragma unroll
                for (int nj = 0; nj < NJ; nj++) {
                    MMAB(acc[mi][nj], ah[mi], bh[nj]);
                    if (BLO) MMAB(acc[mi][nj], ah[mi], bl[nj]);
                    if (ALO) MMAB(acc[mi][nj], al[mi], bh[nj]);
                }
        }
        __syncthreads();
    }
#undef LDG_CH
#undef STS_CH

    const float* bias_b = BIAS ? (bias + (long)bz * sBiasz) : (const float*)0;
#pragma unroll
    for (int mi = 0; mi < MI; mi++)
#pragma unroll
        for (int nj = 0; nj < NJ; nj++) {
            int r = m0 + wm * (16 * MI) + mi * 16 + (lane >> 2);
            int c = n0 + wn * (8 * NJ) + nj * 8 + ((lane & 3) << 1);
            float2 v0 = make_float2(acc[mi][nj][0], acc[mi][nj][1]);
            float2 v1 = make_float2(acc[mi][nj][2], acc[mi][nj][3]);
            if (BIAS) {
                float b0 = bias_b[c] * bscale, b1 = bias_b[c + 1] * bscale;
                v0.x += b0; v0.y += b1; v1.x += b0; v1.y += b1;
            }
            *(float2*)&Cb[(long)r * ldc + c] = v0;
            *(float2*)&Cb[(long)(r + 8) * ldc + c] = v1;
        }
}

static inline int stage_bytes(int MI, int NJ, bool TB, bool ALO, bool BLO) {
    int asz = 32 * MI * 80;
    int bsz = TB ? 32 * (32 * NJ * 2 + 16) : 32 * NJ * 80;
    return (ALO ? 2 : 1) * asz + (BLO ? 2 : 1) * bsz;
}

// ---------------- RoPE table: sin/cos per (l, d) once ---------------------
__global__ __launch_bounds__(512) void rope_tab_kernel() {
    const int l = blockIdx.x;
    const int d = threadIdx.x;
    float ex = (float)(d & ~1) * (1.0f / (float)DC_);
    float inv = exp2f(-13.287712379549449f * ex);
    float s, c;
    sincosf((float)l * inv, &s, &c);
    g_rsin[l * DC_ + d] = s;
    g_rcos[l * DC_ + d] = c;
}

// ---------------- fused RoPE (table lookup) + partial kvsum ---------------
__global__ __launch_bounds__(256) void rope_kernel(const float* __restrict__ kv_c) {
    const int b = blockIdx.x, lb = blockIdx.y;
    const int d = threadIdx.x;
    float s0 = 0.f, s1 = 0.f;
#pragma unroll 4
    for (int l = lb * 64; l < lb * 64 + 64; l++) {
        const long base = ((long)b * L_ + l) * DC_;
        const int tbase = l * DC_ + d;
        float x0 = kv_c[base + d];
        float x1 = kv_c[base + d + 256];
        float sn0 = g_rsin[tbase],       c0 = g_rcos[tbase];
        float sn1 = g_rsin[tbase + 256], c1 = g_rcos[tbase + 256];
        float v0 = x0 * c0 - x1 * sn0;
        float v1 = x1 * c1 + x0 * sn1;
        g_kv[base + d] = v0;
        g_kv[base + d + 256] = v1;
        s0 += v0;
        s1 += v1;
    }
    g_kvp[(lb * B_ + b) * DC_ + d] = s0;
    g_kvp[(lb * B_ + b) * DC_ + d + 256] = s1;
}

__global__ __launch_bounds__(256) void kvred_kernel() {
    const int i = blockIdx.x * 256 + threadIdx.x;
    float s = 0.f;
#pragma unroll
    for (int lb = 0; lb < 8; lb++) s += g_kvp[lb * (B_ * DC_) + i];
    g_kvsum[i] = s;
}

// ---------------- fused scores + softmax ----------------------------------
// grid (4, H): block handles 16 b-rows x 512 d for one head.
// scores[b,h,d] = kvsum[b,d] * sum_r qr[b,h,r]*Wkr[h,d,r]; softmax over d;
// writes attn - 1/512 directly to g_scores.
__global__ __launch_bounds__(256) void scores_softmax_kernel(
    const float* __restrict__ Wkr) {
    extern __shared__ float fsm[];
    float* qs = fsm;                         // [16][68]
    float* ws = fsm + 16 * 68;               // [64][68]  (ws[r][d])
    float* sc = fsm + 16 * 68 + 64 * 68;     // [16][520]
    float* rowinv = sc + 16 * 520;           // [16]
    const int qb = blockIdx.x, h = blockIdx.y;
    const int tid = threadIdx.x;
    const int b4 = tid >> 4;        // 0..15 local b
    const int dg = tid & 15;        // 0..15 d group (x4)

#pragma unroll
    for (int i = 0; i < 4; i++) {
        int idx = tid + i * 256;
        int b = idx >> 6, r = idx & 63;
        qs[b * 68 + r] = g_qr[((long)(qb * 16 + b) * H_ + h) * R_ + r];
    }

    for (int d0 = 0; d0 < DC_; d0 += 64) {
        __syncthreads();
        // load ws[r][dd] = Wkr[h, d0+dd, r]  (transpose during load)
#pragma unroll
        for (int i = 0; i < 16; i++) {
            int idx = tid * 16 + i;
            int dd = idx >> 6, r = idx & 63;
            ws[r * 68 + dd] = Wkr[((long)h * DC_ + d0 + dd) * R_ + r];
        }
        __syncthreads();
        float a0 = 0.f, a1 = 0.f, a2 = 0.f, a3 = 0.f;
#pragma unroll 8
        for (int r = 0; r < 64; r++) {
            float a = qs[b4 * 68 + r];
            float4 w = *(const float4*)&ws[r * 68 + dg * 4];
            a0 += a * w.x; a1 += a * w.y; a2 += a * w.z; a3 += a * w.w;
        }
        float4 kvs = *(const float4*)&g_kvsum[(qb * 16 + b4) * DC_ + d0 + dg * 4];
        float4 o = make_float4(a0 * kvs.x, a1 * kvs.y, a2 * kvs.z, a3 * kvs.w);
        *(float4*)&sc[b4 * 520 + d0 + dg * 4] = o;
    }
    __syncthreads();

    // softmax per row: 8 warps, 2 rows each
    const int w = tid >> 5, lane = tid & 31;
#pragma unroll
    for (int rr = 0; rr < 2; rr++) {
        int row = w * 2 + rr;
        float mx = -1e30f;
#pragma unroll
        for (int i = 0; i < 16; i++)
            mx = fmaxf(mx, sc[row * 520 + lane + i * 32]);
#pragma unroll
        for (int s = 16; s > 0; s >>= 1)
            mx = fmaxf(mx, __shfl_xor_sync(0xFFFFFFFFu, mx, s));
        float sum = 0.f;
#pragma unroll
        for (int i = 0; i < 16; i++) {
            float e = expf(sc[row * 520 + lane + i * 32] - mx);
            sc[row * 520 + lane + i * 32] = e;
            sum += e;
        }
#pragma unroll
        for (int s = 16; s > 0; s >>= 1)
            sum += __shfl_xor_sync(0xFFFFFFFFu, sum, s);
        if (lane == 0) rowinv[row] = 1.0f / sum;
    }
    __syncthreads();

    const float inv = rowinv[b4];
    const long gbase = ((long)(qb * 16 + b4) * H_ + h) * DC_;
#pragma unroll
    for (int j = 0; j < 32; j++) {
        int d = dg + j * 16;
        g_scores[gbase + d] = sc[b4 * 520 + d] * inv - (1.0f / 512.0f);
    }
}

// ---------------- generic split-K reduce ----------------------------------
__global__ __launch_bounds__(256) void reduceN_kernel(float* __restrict__ dst,
                                                      const float* __restrict__ src,
                                                      int parts, long stride) {
    const long i = (long)blockIdx.x * 256 + threadIdx.x;
    float s = 0.f;
    for (int p = 0; p < parts; p++) s += src[(long)p * stride + i];
    dst[i] = s;
}

// ---------------- launch --------------------------------------------------
extern "C" void kernel_launch(void* const* d_in, const int* in_sizes, int n_in,
                              void* d_out, int out_size) {
    const float* hidden_q   = (const float*)d_in[0];
    const float* kv_c       = (const float*)d_in[1];
    const float* q_proj_w   = (const float*)d_in[2];
    const float* w_kc_q     = (const float*)d_in[3];
    const float* w_kc_kv    = (const float*)d_in[4];
    const float* W_qr       = (const float*)d_in[5];
    const float* W_kr       = (const float*)d_in[6];
    const float* out_proj_w = (const float*)d_in[7];
    float* out = (float*)d_out;

    float *qhk, *Ah, *qr, *kvsum, *scores, *ctx, *ctxlat, *part, *kv;
    cudaGetSymbolAddress((void**)&qhk,    g_qhk);
    cudaGetSymbolAddress((void**)&Ah,     g_Ah);
    cudaGetSymbolAddress((void**)&qr,     g_qr);
    cudaGetSymbolAddress((void**)&kv,     g_kv);
    cudaGetSymbolAddress((void**)&kvsum,  g_kvsum);
    cudaGetSymbolAddress((void**)&scores, g_scores);
    cudaGetSymbolAddress((void**)&ctx,    g_ctx);
    cudaGetSymbolAddress((void**)&ctxlat, g_ctxlat);
    cudaGetSymbolAddress((void**)&part,   g_part);

    // smem sizes (2 stages)
    const int smQP = 2 * stage_bytes(2, 2, false, false, false);  // 20480
    const int smAH = 2 * stage_bytes(4, 2, true,  false, false);  // 29696
    const int smQR = 2 * stage_bytes(2, 2, true,  false, false);  // 19456
    const int smCX = 2 * stage_bytes(4, 2, true,  false, true);   // 38912
    const int smCL = 2 * stage_bytes(2, 2, false, true,  true);   // 40960
    const int smSS = (16 * 68 + 64 * 68 + 16 * 520 + 16) * 4;     // ~55 KB
    cudaFuncSetAttribute(scores_softmax_kernel,
                         cudaFuncAttributeMaxDynamicSharedMemorySize, smSS);

    rope_tab_kernel<<<L_, 512>>>();
    rope_kernel<<<dim3(B_, 8), 256>>>(kv_c);
    kvred_kernel<<<(B_ * DC_) / 256, 256>>>();

    // q_hk = hidden_q @ q_proj_w^T  [64 x 16384], split-K x4, 1-MMA
    mgemm<2, 2, false, false, false, false><<<dim3(256, 1, 4), 256, smQP>>>(
        hidden_q, q_proj_w, part, (const float*)0, 0.f, 0,
        512, 0, 0, 0, DQ_, DQ_, H_ * KH_,
        4, 512L, 512L, (long)B_ * H_ * KH_);
    reduceN_kernel<<<(B_ * H_ * KH_) / 256, 256>>>(qhk, part, 4, (long)B_ * H_ * KH_);

    // A_h = w_kc_q[h] @ W_qr[h]  (BM=128; trans B)  K split x4, 1-MMA
    mgemm<4, 2, true, false, false, false><<<dim3(1, 1, H_ * 4), 256, smAH>>>(
        w_kc_q, W_qr, part, (const float*)0, 0.f, 0,
        384, (long)KH_ * DCQ_, (long)DCQ_ * R_, (long)KH_ * R_,
        DCQ_, R_, R_,
        4, 384L, 384L * R_, (long)H_ * KH_ * R_);
    reduceN_kernel<<<(H_ * KH_ * R_) / 256, 256>>>(Ah, part, 4, (long)H_ * KH_ * R_);

    // q_r = q_hk[:,h,:] @ A_h  (trans B)  [64 x 64] x128, 1-MMA
    mgemm<2, 2, true, false, false, false><<<dim3(1, 1, H_), 256, smQR>>>(
        qhk, Ah, qr, (const float*)0, 0.f, 0,
        KH_, (long)KH_, (long)KH_ * R_, (long)R_, H_ * KH_, R_, H_ * R_,
        1, 0, 0, 0);

    // fused scores + softmax (writes attn - 1/512)
    scores_softmax_kernel<<<dim3(4, H_), 256, smSS>>>(W_kr);

    // ctx = (attn - 1/512) @ kv + kvsum/512  (BM=128; trans B, bias), 2-MMA
    mgemm<4, 2, true, true, false, true><<<dim3(DC_ / 64, 1, B_), 256, smCX>>>(
        scores, kv, ctx, kvsum, 1.0f / 512.0f, (long)DC_,
        DC_, (long)H_ * DC_, (long)L_ * DC_, (long)H_ * DC_,
        DC_, DC_, DC_,
        1, 0, 0, 0);

    // ctxlat = ctx[:,h,:] @ w_kc_kv[h]^T  [64 x 128] x128, 3-MMA
    mgemm<2, 2, false, false, true, true><<<dim3(KH_ / 64, 1, H_), 256, smCL>>>(
        ctx, w_kc_kv, ctxlat, (const float*)0, 0.f, 0,
        DC_, (long)DC_, (long)KH_ * DC_, (long)KH_, H_ * DC_, DC_, H_ * KH_,
        1, 0, 0, 0);

    // out = ctxlat @ out_proj_w^T  K=16384, split-K x16, 3-MMA
    mgemm<2, 2, false, false, true, true><<<dim3(DQ_ / 64, 1, 16), 256, smCL>>>(
        ctxlat, out_proj_w, part, (const float*)0, 0.f, 0,
        1024, 0, 0, 0, H_ * KH_, H_ * KH_, DQ_,
        16, 1024L, 1024L, (long)B_ * DQ_);
    reduceN_kernel<<<(B_ * DQ_) / 256, 256>>>(out, part, 16, (long)B_ * DQ_);
}